// round 10
// baseline (speedup 1.0000x reference)
#include <cuda_runtime.h>
#include <cuda_bf16.h>

#define WS 7
#define DROP_PROB 0.1f
#define Hc 250          // H - WS + 1
#define Wc 250
#define Hdim 256
#define Wdim 256
#define MASK_ELEMS (Hdim * Wdim)        // 65536
#define MASK_VEC4  (MASK_ELEMS / 4)     // 16384 float4 groups (h, w4)
#define HW_VEC4 (Hdim * Wdim / 4)       // 16384 float4 per (b,c) plane
#define ROW_VEC4 (Wdim / 4)             // 64 float4 per row
#define BC_TOTAL 1024                   // 16 * 64 planes
#define GROUPS_PER_BLOCK 8
#define FIX_BLOCKS (MASK_VEC4 / GROUPS_PER_BLOCK)   // 2048

// [256,256] broadcast mask (device global scratch; no allocs allowed).
__device__ __align__(16) float g_mask[MASK_ELEMS];

// Kernel 1 (separable 7x7 max-dilation): one block per output row h.
__global__ void build_mask_kernel(const float* __restrict__ u) {
    __shared__ int colOR[Wdim];
    int h = blockIdx.x;
    int w = threadIdx.x;

    int v = 0;
    if (w < Wc) {
        int a0 = h - (WS - 1); if (a0 < 0) a0 = 0;
        int a1 = h;            if (a1 > Hc - 1) a1 = Hc - 1;
        #pragma unroll 7
        for (int a = a0; a <= a1; ++a)
            v |= (__ldg(u + a * Wc + w) < DROP_PROB);
    }
    colOR[w] = v;
    __syncthreads();

    int b0 = w - (WS - 1); if (b0 < 0) b0 = 0;
    int b1 = w;            if (b1 > Wc - 1) b1 = Wc - 1;
    int d = 0;
    #pragma unroll 7
    for (int b = b0; b <= b1; ++b)
        d |= colOR[b];

    g_mask[h * Wdim + w] = d ? 0.0f : 1.0f;
}

// Kernel 2 (after memset): rewrite only surviving float4 columns.
// Each block scans 8 (h,w4) groups; all-dropped groups (≈98-99%) are skipped —
// their zeros were already written by the memset. A surviving group rewrites
// that 16B column across all 1024 (b,c) planes: 4 loads + 4 stores per thread.
__global__ void __launch_bounds__(256, 8)
fixup_survivors_kernel(const float4* __restrict__ x, float4* __restrict__ out) {
    const float4* m4 = reinterpret_cast<const float4*>(g_mask);
    int g0 = blockIdx.x * GROUPS_PER_BLOCK;

    #pragma unroll
    for (int j = 0; j < GROUPS_PER_BLOCK; ++j) {
        int g = g0 + j;
        float4 mv = __ldg(m4 + g);               // L2 broadcast
        if ((mv.x + mv.y + mv.z + mv.w) == 0.0f) continue;

        unsigned int base = (unsigned int)g;     // g = h*ROW_VEC4 + w4 exactly
        #pragma unroll
        for (int k = 0; k < 4; ++k) {
            unsigned int bc = threadIdx.x + 256u * k;
            unsigned int idx = bc * HW_VEC4 + base;
            float4 xv = __ldg(x + idx);
            float4 ov;
            ov.x = xv.x * mv.x; ov.y = xv.y * mv.y;
            ov.z = xv.z * mv.z; ov.w = xv.w * mv.w;
            out[idx] = ov;
        }
    }
}

extern "C" void kernel_launch(void* const* d_in, const int* in_sizes, int n_in,
                              void* d_out, int out_size) {
    const float* x = (const float*)d_in[0];   // [16,64,256,256] fp32
    const float* u = (const float*)d_in[1];   // [250,250] fp32

    // 1) 256x256 dilated mask into g_mask (L2-resident, 256KB)
    build_mask_kernel<<<Hdim, Wdim>>>(u);

    // 2) zero the entire output via the driver's memset path (99.4% is zero)
    cudaMemsetAsync(d_out, 0, (size_t)out_size * sizeof(float));

    // 3) rewrite surviving columns only (~1-2% of groups, ~7MB traffic)
    fixup_survivors_kernel<<<FIX_BLOCKS, 256>>>(
        reinterpret_cast<const float4*>(x),
        reinterpret_cast<float4*>(d_out));
}

// round 13
// speedup vs baseline: 1.0912x; 1.0912x over previous
#include <cuda_runtime.h>
#include <cuda_bf16.h>

#define WS 7
#define DROP_PROB 0.1f
#define Hc 250          // H - WS + 1
#define Wc 250
#define Hdim 256
#define Wdim 256
#define MASK_ELEMS (Hdim * Wdim)        // 65536
#define MASK_VEC4  (MASK_ELEMS / 4)     // 16384 float4 per plane
#define PLANES     1024                 // 16 * 64
#define ALPHA      32                   // plane-groups; thread covers PLANES/ALPHA=32 planes
#define NTHREADS   (MASK_VEC4 * ALPHA)  // 524288 threads
#define NBLOCKS    (NTHREADS / 256)     // 2048
#define PLANE_STRIDE_V4 (ALPHA * MASK_VEC4)   // 524288 float4 between visited planes

// [256,256] broadcast mask (device global scratch; no allocs allowed).
__device__ __align__(16) float g_mask[MASK_ELEMS];

// Kernel 1 (separable 7x7 max-dilation): one block per output row h. ~2us.
__global__ void build_mask_kernel(const float* __restrict__ u) {
    __shared__ int colOR[Wdim];
    int h = blockIdx.x;
    int w = threadIdx.x;

    int v = 0;
    if (w < Wc) {
        int a0 = h - (WS - 1); if (a0 < 0) a0 = 0;
        int a1 = h;            if (a1 > Hc - 1) a1 = Hc - 1;
        #pragma unroll 7
        for (int a = a0; a <= a1; ++a)
            v |= (__ldg(u + a * Wc + w) < DROP_PROB);
    }
    colOR[w] = v;
    __syncthreads();

    int b0 = w - (WS - 1); if (b0 < 0) b0 = 0;
    int b1 = w;            if (b1 > Wc - 1) b1 = Wc - 1;
    int d = 0;
    #pragma unroll 7
    for (int b = b0; b <= b1; ++b)
        d |= colOR[b];

    g_mask[h * Wdim + w] = d ? 0.0f : 1.0f;
}

// Kernel 2: register-mask streaming store. Thread t owns ONE mask float4
// (m = t & 16383, loaded once) and visits 32 planes at stride 32*plane.
// Lanes are consecutive m -> every STG.128 is fully coalesced. The
// mask-dead branch is hoisted OUT of the loop: dead threads run a pure
// memset-style store loop with zero loads and zero per-iteration deps.
__global__ void __launch_bounds__(256, 8)
stream_apply_kernel(const float4* __restrict__ x, float4* __restrict__ out) {
    unsigned int t = blockIdx.x * 256u + threadIdx.x;
    unsigned int m = t & (MASK_VEC4 - 1);      // float4 index within plane
    unsigned int p0 = t >> 14;                 // 0..31: first plane group
    unsigned int base = p0 * MASK_VEC4 + m;

    const float4* m4 = reinterpret_cast<const float4*>(g_mask);
    float4 mv = __ldg(m4 + m);                 // ONE mask load per thread

    if ((mv.x + mv.y + mv.z + mv.w) == 0.0f) {
        // dead column: pure store stream (this is the dominant path)
        const float4 z = make_float4(0.f, 0.f, 0.f, 0.f);
        #pragma unroll 8
        for (int j = 0; j < PLANES / ALPHA; ++j) {
            out[base + (unsigned int)j * PLANE_STRIDE_V4] = z;
        }
    } else {
        // surviving column: load, scale, store
        #pragma unroll 8
        for (int j = 0; j < PLANES / ALPHA; ++j) {
            unsigned int idx = base + (unsigned int)j * PLANE_STRIDE_V4;
            float4 xv = __ldg(x + idx);
            float4 ov;
            ov.x = xv.x * mv.x; ov.y = xv.y * mv.y;
            ov.z = xv.z * mv.z; ov.w = xv.w * mv.w;
            out[idx] = ov;
        }
    }
}

extern "C" void kernel_launch(void* const* d_in, const int* in_sizes, int n_in,
                              void* d_out, int out_size) {
    const float* x = (const float*)d_in[0];   // [16,64,256,256] fp32
    const float* u = (const float*)d_in[1];   // [250,250] fp32
    float* out = (float*)d_out;

    // 1) 256x256 dilated mask (L2-resident, 256KB)
    build_mask_kernel<<<Hdim, Wdim>>>(u);

    // 2) register-mask streaming apply: 2048 blocks x 256 threads,
    //    32 coalesced float4 stores per thread
    stream_apply_kernel<<<NBLOCKS, 256>>>(
        reinterpret_cast<const float4*>(x),
        reinterpret_cast<float4*>(out));
}